// round 8
// baseline (speedup 1.0000x reference)
#include <cuda_runtime.h>
#include <cuda_fp16.h>
#include <cstdint>

// Problem constants (NeighborhoodSelfAttention: B=1, N=50000, K=16, D=128, H=8)
#define MAXN 50000
#define D 128
#define KNBR 16

// Scratch: device globals (no allocation allowed). All intermediates fp16.
__device__ __align__(16) __half g_Q[MAXN * D];
__device__ __align__(16) __half g_K[MAXN * D];
__device__ __align__(16) __half g_V[MAXN * D];
__device__ __align__(16) __half g_att[MAXN * D];

// ---------------------------------------------------------------------------
// Full-K tensor-core GEMM tiles: A[128][128] and B[128][128] both resident in
// (dynamic) shared memory as fp16, +8-half row pad for conflict-free ldmatrix.
// ---------------------------------------------------------------------------
#define TM 128
#define T_LD 136   // 128 + 8 halves pad -> 68-word row stride

struct FusedSmem {
    __half A[TM][T_LD];
    __half B[TM][T_LD];
};
#define FUSED_SMEM_BYTES ((int)sizeof(FusedSmem))

__device__ __forceinline__ uint32_t smem_u32(const void* p) {
    return (uint32_t)__cvta_generic_to_shared(p);
}
__device__ __forceinline__ void ldsm_x4(uint32_t& r0, uint32_t& r1,
                                        uint32_t& r2, uint32_t& r3,
                                        uint32_t addr) {
    asm volatile("ldmatrix.sync.aligned.m8n8.x4.shared.b16 {%0,%1,%2,%3}, [%4];"
                 : "=r"(r0), "=r"(r1), "=r"(r2), "=r"(r3) : "r"(addr));
}
__device__ __forceinline__ void ldsm_x2t(uint32_t& r0, uint32_t& r1,
                                         uint32_t addr) {
    asm volatile("ldmatrix.sync.aligned.m8n8.x2.trans.shared.b16 {%0,%1}, [%2];"
                 : "=r"(r0), "=r"(r1) : "r"(addr));
}
__device__ __forceinline__ void mma16816(float& c0, float& c1, float& c2, float& c3,
                                         uint32_t a0, uint32_t a1, uint32_t a2,
                                         uint32_t a3, uint32_t b0, uint32_t b1) {
    asm volatile(
        "mma.sync.aligned.m16n8k16.row.col.f32.f16.f16.f32 "
        "{%0,%1,%2,%3}, {%4,%5,%6,%7}, {%8,%9}, {%0,%1,%2,%3};"
        : "+f"(c0), "+f"(c1), "+f"(c2), "+f"(c3)
        : "r"(a0), "r"(a1), "r"(a2), "r"(a3), "r"(b0), "r"(b1));
}

// Stage a 128x128 fp32 matrix into smem tile as fp16 (16 float4 per thread).
__device__ __forceinline__ void stage_f32(__half (*T)[T_LD],
                                          const float* __restrict__ S,
                                          int m0, int M, int tid) {
#pragma unroll
    for (int i = 0; i < 16; i++) {
        int lin = tid + i * 256;
        int row = lin >> 5;
        int col = (lin & 31) << 2;
        int gm  = m0 + row;
        float4 v = make_float4(0.f, 0.f, 0.f, 0.f);
        if (gm < M)
            v = *reinterpret_cast<const float4*>(&S[(size_t)gm * D + col]);
        __half2 h0 = __floats2half2_rn(v.x, v.y);
        __half2 h1 = __floats2half2_rn(v.z, v.w);
        uint2 pk;
        pk.x = *reinterpret_cast<unsigned*>(&h0);
        pk.y = *reinterpret_cast<unsigned*>(&h1);
        *reinterpret_cast<uint2*>(&T[row][col]) = pk;
    }
}
__device__ __forceinline__ void stage_f16(__half (*T)[T_LD],
                                          const __half* __restrict__ S,
                                          int m0, int M, int tid) {
#pragma unroll
    for (int i = 0; i < 16; i++) {
        int lin = tid + i * 256;
        int row = lin >> 5;
        int col = (lin & 31) << 2;
        int gm  = m0 + row;
        uint2 pk = make_uint2(0u, 0u);
        if (gm < M)
            pk = *reinterpret_cast<const uint2*>(&S[(size_t)gm * D + col]);
        *reinterpret_cast<uint2*>(&T[row][col]) = pk;
    }
}
// Stage a 128x128 fp32 weight (no row bound needed).
__device__ __forceinline__ void stage_w(__half (*T)[T_LD],
                                        const float* __restrict__ W, int tid) {
#pragma unroll
    for (int i = 0; i < 16; i++) {
        int lin = tid + i * 256;
        int row = lin >> 5;
        int col = (lin & 31) << 2;
        float4 v = *reinterpret_cast<const float4*>(&W[(size_t)row * D + col]);
        __half2 h0 = __floats2half2_rn(v.x, v.y);
        __half2 h1 = __floats2half2_rn(v.z, v.w);
        uint2 pk;
        pk.x = *reinterpret_cast<unsigned*>(&h0);
        pk.y = *reinterpret_cast<unsigned*>(&h1);
        *reinterpret_cast<uint2*>(&T[row][col]) = pk;
    }
}

// Full-K mma over resident A,B tiles. 8 warps of 64x32; acc c[4][4][4].
__device__ __forceinline__ void mma_fullk(FusedSmem* sm, float c[4][4][4],
                                          int lane, int wm, int wn) {
#pragma unroll
    for (int mi = 0; mi < 4; mi++)
#pragma unroll
        for (int nj = 0; nj < 4; nj++)
#pragma unroll
            for (int r = 0; r < 4; r++) c[mi][nj][r] = 0.f;

#pragma unroll
    for (int kk = 0; kk < D; kk += 16) {
        uint32_t a[4][4], b[4][2];
#pragma unroll
        for (int mi = 0; mi < 4; mi++) {
            uint32_t addr = smem_u32(
                &sm->A[wm + mi * 16 + (lane & 15)][kk + ((lane >> 4) << 3)]);
            ldsm_x4(a[mi][0], a[mi][1], a[mi][2], a[mi][3], addr);
        }
#pragma unroll
        for (int nj = 0; nj < 4; nj++) {
            uint32_t addr = smem_u32(&sm->B[kk + (lane & 15)][wn + nj * 8]);
            ldsm_x2t(b[nj][0], b[nj][1], addr);
        }
#pragma unroll
        for (int mi = 0; mi < 4; mi++)
#pragma unroll
            for (int nj = 0; nj < 4; nj++)
                mma16816(c[mi][nj][0], c[mi][nj][1], c[mi][nj][2], c[mi][nj][3],
                         a[mi][0], a[mi][1], a[mi][2], a[mi][3],
                         b[nj][0], b[nj][1]);
    }
}

// Epilogue: bias add + store (fp16 or fp32).
template <bool OUT_FP32>
__device__ __forceinline__ void epilogue(float c[4][4][4],
                                         const float* __restrict__ bias,
                                         float* __restrict__ Yf,
                                         __half* __restrict__ Yh,
                                         int m0, int M, int lane, int wm, int wn) {
#pragma unroll
    for (int mi = 0; mi < 4; mi++) {
        int r0 = m0 + wm + mi * 16 + (lane >> 2);
#pragma unroll
        for (int nj = 0; nj < 4; nj++) {
            int col  = wn + nj * 8 + ((lane & 3) << 1);
            float b0 = bias[col], b1 = bias[col + 1];
            float v00 = c[mi][nj][0] + b0, v01 = c[mi][nj][1] + b1;
            float v10 = c[mi][nj][2] + b0, v11 = c[mi][nj][3] + b1;
            if (r0 < M) {
                if (OUT_FP32) {
                    *reinterpret_cast<float2*>(&Yf[(size_t)r0 * D + col]) =
                        make_float2(v00, v01);
                } else {
                    __half2 h = __floats2half2_rn(v00, v01);
                    *reinterpret_cast<unsigned*>(&Yh[(size_t)r0 * D + col]) =
                        *reinterpret_cast<unsigned*>(&h);
                }
            }
            if (r0 + 8 < M) {
                if (OUT_FP32) {
                    *reinterpret_cast<float2*>(&Yf[(size_t)(r0 + 8) * D + col]) =
                        make_float2(v10, v11);
                } else {
                    __half2 h = __floats2half2_rn(v10, v11);
                    *reinterpret_cast<unsigned*>(&Yh[(size_t)(r0 + 8) * D + col]) =
                        *reinterpret_cast<unsigned*>(&h);
                }
            }
        }
    }
}

// Kernel A: fused QKV. A tile staged ONCE; loop over the 3 weight matrices.
__global__ __launch_bounds__(256, 2) void qkv_fused_kernel(
    const float* __restrict__ X,
    const float* __restrict__ Wq, const float* __restrict__ bq,
    const float* __restrict__ Wk, const float* __restrict__ bk,
    const float* __restrict__ Wv, const float* __restrict__ bv, int M) {
    extern __shared__ __align__(16) char dyn_smem[];
    FusedSmem* sm = reinterpret_cast<FusedSmem*>(dyn_smem);

    const int tid  = threadIdx.x;
    const int lane = tid & 31;
    const int wid  = tid >> 5;
    const int m0   = blockIdx.x * TM;
    const int wm   = (wid >> 2) * 64;
    const int wn   = (wid & 3) * 32;

    stage_f32(sm->A, X, m0, M, tid);

    const float* Ws[3]  = {Wq, Wk, Wv};
    const float* bs[3]  = {bq, bk, bv};
    __half*      Ys[3]  = {g_Q, g_K, g_V};

    float c[4][4][4];
#pragma unroll 1
    for (int mtx = 0; mtx < 3; mtx++) {
        stage_w(sm->B, Ws[mtx], tid);
        __syncthreads();
        mma_fullk(sm, c, lane, wm, wn);
        __syncthreads();   // protect B before next matrix overwrites it
        epilogue<false>(c, bs[mtx], nullptr, Ys[mtx], m0, M, lane, wm, wn);
    }
}

// Kernel C: output projection; A = g_att (fp16), output fp32.
__global__ __launch_bounds__(256, 2) void out_kernel(
    const float* __restrict__ Wo, const float* __restrict__ bo,
    float* __restrict__ Y, int M) {
    extern __shared__ __align__(16) char dyn_smem[];
    FusedSmem* sm = reinterpret_cast<FusedSmem*>(dyn_smem);

    const int tid  = threadIdx.x;
    const int lane = tid & 31;
    const int wid  = tid >> 5;
    const int m0   = blockIdx.x * TM;
    const int wm   = (wid >> 2) * 64;
    const int wn   = (wid & 3) * 32;

    stage_f16(sm->A, g_att, m0, M, tid);
    stage_w(sm->B, Wo, tid);
    __syncthreads();

    float c[4][4][4];
    mma_fullk(sm, c, lane, wm, wn);
    epilogue<true>(c, bo, Y, nullptr, m0, M, lane, wm, wn);
}

// ---------------------------------------------------------------------------
// Kernel B: one warp per node. Batch-load 16 indices, then all 32 K/V rows
// (max MLP vs L2 latency), then dots/softmax/weighted sum. nbrs is INT32.
// ---------------------------------------------------------------------------
__global__ __launch_bounds__(256) void attn_kernel(
    const int* __restrict__ nbrs, int N) {
    int warp = (blockIdx.x * blockDim.x + threadIdx.x) >> 5;
    if (warp >= N) return;
    int lane = threadIdx.x & 31;

    const uint2* __restrict__ Qh = reinterpret_cast<const uint2*>(g_Q);
    const uint2* __restrict__ Kh = reinterpret_cast<const uint2*>(g_K);
    const uint2* __restrict__ Vh = reinterpret_cast<const uint2*>(g_V);

    uint2 qr = Qh[warp * 32 + lane];   // 4 fp16: dims [4*lane,4*lane+4); head=lane/4
    float2 q0 = __half22float2(*reinterpret_cast<__half2*>(&qr.x));
    float2 q1 = __half22float2(*reinterpret_cast<__half2*>(&qr.y));

    int  idx[KNBR];
    bool vld[KNBR];
#pragma unroll
    for (int j = 0; j < KNBR; j++) {
        int nb = __ldg(&nbrs[(size_t)warp * KNBR + j]);
        vld[j] = (nb >= 0);
        int t  = nb >= 0 ? nb : 0;
        idx[j] = (t < N) ? t : 0;
    }

    uint2 kraw[KNBR], vraw[KNBR];
#pragma unroll
    for (int j = 0; j < KNBR; j++) kraw[j] = Kh[idx[j] * 32 + lane];
#pragma unroll
    for (int j = 0; j < KNBR; j++) vraw[j] = Vh[idx[j] * 32 + lane];

    float s[KNBR];
#pragma unroll
    for (int j = 0; j < KNBR; j++) {
        float2 k0 = __half22float2(*reinterpret_cast<__half2*>(&kraw[j].x));
        float2 k1 = __half22float2(*reinterpret_cast<__half2*>(&kraw[j].y));
        float p = q0.x * k0.x + q0.y * k0.y + q1.x * k1.x + q1.y * k1.y;
        p += __shfl_xor_sync(0xffffffffu, p, 1);
        p += __shfl_xor_sync(0xffffffffu, p, 2);  // full 16-dim head dot
        s[j] = vld[j] ? p * 0.25f : -1.0e9f;      // scale = 1/sqrt(16)
    }

    float m = -3.0e38f;
#pragma unroll
    for (int j = 0; j < KNBR; j++) m = fmaxf(m, s[j]);
    float sum = 0.f;
#pragma unroll
    for (int j = 0; j < KNBR; j++) {
        float e = __expf(s[j] - m);
        s[j] = e;
        sum += e;
    }
    float inv = 1.f / sum;

    float4 acc = make_float4(0.f, 0.f, 0.f, 0.f);
#pragma unroll
    for (int j = 0; j < KNBR; j++) {
        float w = s[j] * inv;
        float2 v0 = __half22float2(*reinterpret_cast<__half2*>(&vraw[j].x));
        float2 v1 = __half22float2(*reinterpret_cast<__half2*>(&vraw[j].y));
        acc.x += w * v0.x;
        acc.y += w * v0.y;
        acc.z += w * v1.x;
        acc.w += w * v1.y;
    }
    __half2 o0 = __floats2half2_rn(acc.x, acc.y);
    __half2 o1 = __floats2half2_rn(acc.z, acc.w);
    uint2 pk;
    pk.x = *reinterpret_cast<unsigned*>(&o0);
    pk.y = *reinterpret_cast<unsigned*>(&o1);
    reinterpret_cast<uint2*>(g_att)[warp * 32 + lane] = pk;
}

// ---------------------------------------------------------------------------
// Launch: A (fused QKV) -> B (attention) -> C (output proj), default stream.
// Inputs: x, neighbors, Wq, bq, Wk, bk, Wv, bv, Wo, bo
// ---------------------------------------------------------------------------
extern "C" void kernel_launch(void* const* d_in, const int* in_sizes, int n_in,
                              void* d_out, int out_size) {
    const float* x    = (const float*)d_in[0];
    const int*   nbrs = (const int*)d_in[1];
    const float* Wq   = (const float*)d_in[2];
    const float* bq   = (const float*)d_in[3];
    const float* Wk   = (const float*)d_in[4];
    const float* bk   = (const float*)d_in[5];
    const float* Wv   = (const float*)d_in[6];
    const float* bv   = (const float*)d_in[7];
    const float* Wo   = (const float*)d_in[8];
    const float* bo   = (const float*)d_in[9];
    float*       out  = (float*)d_out;

    int N = in_sizes[0] / D;   // 50000

    // Opt into >48KB dynamic smem (non-stream call; capture-legal).
    cudaFuncSetAttribute(qkv_fused_kernel,
                         cudaFuncAttributeMaxDynamicSharedMemorySize,
                         FUSED_SMEM_BYTES);
    cudaFuncSetAttribute(out_kernel,
                         cudaFuncAttributeMaxDynamicSharedMemorySize,
                         FUSED_SMEM_BYTES);

    int gA = (N + TM - 1) / TM;
    qkv_fused_kernel<<<gA, 256, FUSED_SMEM_BYTES>>>(x, Wq, bq, Wk, bk, Wv, bv, N);

    int blocksB = (N + 7) / 8;  // 8 warps / block
    attn_kernel<<<blocksB, 256>>>(nbrs, N);

    out_kernel<<<gA, 256, FUSED_SMEM_BYTES>>>(Wo, bo, out, N);
}

// round 10
// speedup vs baseline: 1.2823x; 1.2823x over previous
#include <cuda_runtime.h>
#include <cuda_fp16.h>
#include <cstdint>

// Problem constants (NeighborhoodSelfAttention: B=1, N=50000, K=16, D=128, H=8)
#define MAXN 50000
#define D 128
#define KNBR 16

// Scratch: device globals (no allocation allowed). All intermediates fp16.
__device__ __align__(16) __half g_Q[MAXN * D];
__device__ __align__(16) __half g_K[MAXN * D];
__device__ __align__(16) __half g_V[MAXN * D];
__device__ __align__(16) __half g_att[MAXN * D];

// ---------------------------------------------------------------------------
// Full-K tensor-core GEMM tiles: A[128][128] and B[128][128] both resident in
// (dynamic) shared memory as fp16, +8-half row pad for conflict-free ldmatrix.
// ---------------------------------------------------------------------------
#define TM 128
#define T_LD 136   // 128 + 8 halves pad -> 68-word row stride

struct FusedSmem {
    __half A[TM][T_LD];
    __half B[TM][T_LD];
};
#define FUSED_SMEM_BYTES ((int)sizeof(FusedSmem))

__device__ __forceinline__ uint32_t smem_u32(const void* p) {
    return (uint32_t)__cvta_generic_to_shared(p);
}
__device__ __forceinline__ void ldsm_x4(uint32_t& r0, uint32_t& r1,
                                        uint32_t& r2, uint32_t& r3,
                                        uint32_t addr) {
    asm volatile("ldmatrix.sync.aligned.m8n8.x4.shared.b16 {%0,%1,%2,%3}, [%4];"
                 : "=r"(r0), "=r"(r1), "=r"(r2), "=r"(r3) : "r"(addr));
}
__device__ __forceinline__ void ldsm_x2t(uint32_t& r0, uint32_t& r1,
                                         uint32_t addr) {
    asm volatile("ldmatrix.sync.aligned.m8n8.x2.trans.shared.b16 {%0,%1}, [%2];"
                 : "=r"(r0), "=r"(r1) : "r"(addr));
}
__device__ __forceinline__ void mma16816(float& c0, float& c1, float& c2, float& c3,
                                         uint32_t a0, uint32_t a1, uint32_t a2,
                                         uint32_t a3, uint32_t b0, uint32_t b1) {
    asm volatile(
        "mma.sync.aligned.m16n8k16.row.col.f32.f16.f16.f32 "
        "{%0,%1,%2,%3}, {%4,%5,%6,%7}, {%8,%9}, {%0,%1,%2,%3};"
        : "+f"(c0), "+f"(c1), "+f"(c2), "+f"(c3)
        : "r"(a0), "r"(a1), "r"(a2), "r"(a3), "r"(b0), "r"(b1));
}

// Stage a 128x128 fp32 matrix into smem tile as fp16 (16 float4 per thread).
__device__ __forceinline__ void stage_f32(__half (*T)[T_LD],
                                          const float* __restrict__ S,
                                          int m0, int M, int tid) {
#pragma unroll
    for (int i = 0; i < 16; i++) {
        int lin = tid + i * 256;
        int row = lin >> 5;
        int col = (lin & 31) << 2;
        int gm  = m0 + row;
        float4 v = make_float4(0.f, 0.f, 0.f, 0.f);
        if (gm < M)
            v = *reinterpret_cast<const float4*>(&S[(size_t)gm * D + col]);
        __half2 h0 = __floats2half2_rn(v.x, v.y);
        __half2 h1 = __floats2half2_rn(v.z, v.w);
        uint2 pk;
        pk.x = *reinterpret_cast<unsigned*>(&h0);
        pk.y = *reinterpret_cast<unsigned*>(&h1);
        *reinterpret_cast<uint2*>(&T[row][col]) = pk;
    }
}
__device__ __forceinline__ void stage_f16(__half (*T)[T_LD],
                                          const __half* __restrict__ S,
                                          int m0, int M, int tid) {
#pragma unroll
    for (int i = 0; i < 16; i++) {
        int lin = tid + i * 256;
        int row = lin >> 5;
        int col = (lin & 31) << 2;
        int gm  = m0 + row;
        uint2 pk = make_uint2(0u, 0u);
        if (gm < M)
            pk = *reinterpret_cast<const uint2*>(&S[(size_t)gm * D + col]);
        *reinterpret_cast<uint2*>(&T[row][col]) = pk;
    }
}
// Stage a 128x128 fp32 weight (no row bound needed).
__device__ __forceinline__ void stage_w(__half (*T)[T_LD],
                                        const float* __restrict__ W, int tid) {
#pragma unroll
    for (int i = 0; i < 16; i++) {
        int lin = tid + i * 256;
        int row = lin >> 5;
        int col = (lin & 31) << 2;
        float4 v = *reinterpret_cast<const float4*>(&W[(size_t)row * D + col]);
        __half2 h0 = __floats2half2_rn(v.x, v.y);
        __half2 h1 = __floats2half2_rn(v.z, v.w);
        uint2 pk;
        pk.x = *reinterpret_cast<unsigned*>(&h0);
        pk.y = *reinterpret_cast<unsigned*>(&h1);
        *reinterpret_cast<uint2*>(&T[row][col]) = pk;
    }
}

// Full-K mma over resident A,B tiles. 8 warps of 64x32; acc c[4][4][4].
__device__ __forceinline__ void mma_fullk(FusedSmem* sm, float c[4][4][4],
                                          int lane, int wm, int wn) {
#pragma unroll
    for (int mi = 0; mi < 4; mi++)
#pragma unroll
        for (int nj = 0; nj < 4; nj++)
#pragma unroll
            for (int r = 0; r < 4; r++) c[mi][nj][r] = 0.f;

#pragma unroll
    for (int kk = 0; kk < D; kk += 16) {
        uint32_t a[4][4], b[4][2];
#pragma unroll
        for (int mi = 0; mi < 4; mi++) {
            uint32_t addr = smem_u32(
                &sm->A[wm + mi * 16 + (lane & 15)][kk + ((lane >> 4) << 3)]);
            ldsm_x4(a[mi][0], a[mi][1], a[mi][2], a[mi][3], addr);
        }
#pragma unroll
        for (int nj = 0; nj < 4; nj++) {
            uint32_t addr = smem_u32(&sm->B[kk + (lane & 15)][wn + nj * 8]);
            ldsm_x2t(b[nj][0], b[nj][1], addr);
        }
#pragma unroll
        for (int mi = 0; mi < 4; mi++)
#pragma unroll
            for (int nj = 0; nj < 4; nj++)
                mma16816(c[mi][nj][0], c[mi][nj][1], c[mi][nj][2], c[mi][nj][3],
                         a[mi][0], a[mi][1], a[mi][2], a[mi][3],
                         b[nj][0], b[nj][1]);
    }
}

// Epilogue: bias add + store (fp16 or fp32).
template <bool OUT_FP32>
__device__ __forceinline__ void epilogue(float c[4][4][4],
                                         const float* __restrict__ bias,
                                         float* __restrict__ Yf,
                                         __half* __restrict__ Yh,
                                         int m0, int M, int lane, int wm, int wn) {
#pragma unroll
    for (int mi = 0; mi < 4; mi++) {
        int r0 = m0 + wm + mi * 16 + (lane >> 2);
#pragma unroll
        for (int nj = 0; nj < 4; nj++) {
            int col  = wn + nj * 8 + ((lane & 3) << 1);
            float b0 = bias[col], b1 = bias[col + 1];
            float v00 = c[mi][nj][0] + b0, v01 = c[mi][nj][1] + b1;
            float v10 = c[mi][nj][2] + b0, v11 = c[mi][nj][3] + b1;
            if (r0 < M) {
                if (OUT_FP32) {
                    *reinterpret_cast<float2*>(&Yf[(size_t)r0 * D + col]) =
                        make_float2(v00, v01);
                } else {
                    __half2 h = __floats2half2_rn(v00, v01);
                    *reinterpret_cast<unsigned*>(&Yh[(size_t)r0 * D + col]) =
                        *reinterpret_cast<unsigned*>(&h);
                }
            }
            if (r0 + 8 < M) {
                if (OUT_FP32) {
                    *reinterpret_cast<float2*>(&Yf[(size_t)(r0 + 8) * D + col]) =
                        make_float2(v10, v11);
                } else {
                    __half2 h = __floats2half2_rn(v10, v11);
                    *reinterpret_cast<unsigned*>(&Yh[(size_t)(r0 + 8) * D + col]) =
                        *reinterpret_cast<unsigned*>(&h);
                }
            }
        }
    }
}

// Kernel A: QKV projection. grid = (391, 3); each CTA does ONE matrix with
// full-K resident tiles and a single __syncthreads. 1173 CTAs -> ~4 waves:
// cross-CTA overlap of staging and mma phases (R8's 391-CTA fused loop
// serialized these and lost to wave quantization).
__global__ __launch_bounds__(256, 2) void qkv_kernel(
    const float* __restrict__ X,
    const float* __restrict__ Wq, const float* __restrict__ bq,
    const float* __restrict__ Wk, const float* __restrict__ bk,
    const float* __restrict__ Wv, const float* __restrict__ bv, int M) {
    extern __shared__ __align__(16) char dyn_smem[];
    FusedSmem* sm = reinterpret_cast<FusedSmem*>(dyn_smem);

    const int tid  = threadIdx.x;
    const int lane = tid & 31;
    const int wid  = tid >> 5;
    const int m0   = blockIdx.x * TM;
    const int wm   = (wid >> 2) * 64;
    const int wn   = (wid & 3) * 32;

    const float* W;
    const float* b;
    __half*      Y;
    if (blockIdx.y == 0)      { W = Wq; b = bq; Y = g_Q; }
    else if (blockIdx.y == 1) { W = Wk; b = bk; Y = g_K; }
    else                      { W = Wv; b = bv; Y = g_V; }

    stage_f32(sm->A, X, m0, M, tid);
    stage_w(sm->B, W, tid);
    __syncthreads();

    float c[4][4][4];
    mma_fullk(sm, c, lane, wm, wn);
    epilogue<false>(c, b, nullptr, Y, m0, M, lane, wm, wn);
}

// Kernel C: output projection; A = g_att (fp16), output fp32.
__global__ __launch_bounds__(256, 2) void out_kernel(
    const float* __restrict__ Wo, const float* __restrict__ bo,
    float* __restrict__ Y, int M) {
    extern __shared__ __align__(16) char dyn_smem[];
    FusedSmem* sm = reinterpret_cast<FusedSmem*>(dyn_smem);

    const int tid  = threadIdx.x;
    const int lane = tid & 31;
    const int wid  = tid >> 5;
    const int m0   = blockIdx.x * TM;
    const int wm   = (wid >> 2) * 64;
    const int wn   = (wid & 3) * 32;

    stage_f16(sm->A, g_att, m0, M, tid);
    stage_w(sm->B, Wo, tid);
    __syncthreads();

    float c[4][4][4];
    mma_fullk(sm, c, lane, wm, wn);
    epilogue<true>(c, bo, Y, nullptr, m0, M, lane, wm, wn);
}

// ---------------------------------------------------------------------------
// Kernel B: one warp per node. Batch-load 16 indices, then all 32 K/V rows
// (max MLP vs L2 latency), then dots/softmax/weighted sum. nbrs is INT32.
// ---------------------------------------------------------------------------
__global__ __launch_bounds__(256) void attn_kernel(
    const int* __restrict__ nbrs, int N) {
    int warp = (blockIdx.x * blockDim.x + threadIdx.x) >> 5;
    if (warp >= N) return;
    int lane = threadIdx.x & 31;

    const uint2* __restrict__ Qh = reinterpret_cast<const uint2*>(g_Q);
    const uint2* __restrict__ Kh = reinterpret_cast<const uint2*>(g_K);
    const uint2* __restrict__ Vh = reinterpret_cast<const uint2*>(g_V);

    uint2 qr = Qh[warp * 32 + lane];   // 4 fp16: dims [4*lane,4*lane+4); head=lane/4
    float2 q0 = __half22float2(*reinterpret_cast<__half2*>(&qr.x));
    float2 q1 = __half22float2(*reinterpret_cast<__half2*>(&qr.y));

    int  idx[KNBR];
    bool vld[KNBR];
#pragma unroll
    for (int j = 0; j < KNBR; j++) {
        int nb = __ldg(&nbrs[(size_t)warp * KNBR + j]);
        vld[j] = (nb >= 0);
        int t  = nb >= 0 ? nb : 0;
        idx[j] = (t < N) ? t : 0;
    }

    uint2 kraw[KNBR], vraw[KNBR];
#pragma unroll
    for (int j = 0; j < KNBR; j++) kraw[j] = Kh[idx[j] * 32 + lane];
#pragma unroll
    for (int j = 0; j < KNBR; j++) vraw[j] = Vh[idx[j] * 32 + lane];

    float s[KNBR];
#pragma unroll
    for (int j = 0; j < KNBR; j++) {
        float2 k0 = __half22float2(*reinterpret_cast<__half2*>(&kraw[j].x));
        float2 k1 = __half22float2(*reinterpret_cast<__half2*>(&kraw[j].y));
        float p = q0.x * k0.x + q0.y * k0.y + q1.x * k1.x + q1.y * k1.y;
        p += __shfl_xor_sync(0xffffffffu, p, 1);
        p += __shfl_xor_sync(0xffffffffu, p, 2);  // full 16-dim head dot
        s[j] = vld[j] ? p * 0.25f : -1.0e9f;      // scale = 1/sqrt(16)
    }

    float m = -3.0e38f;
#pragma unroll
    for (int j = 0; j < KNBR; j++) m = fmaxf(m, s[j]);
    float sum = 0.f;
#pragma unroll
    for (int j = 0; j < KNBR; j++) {
        float e = __expf(s[j] - m);
        s[j] = e;
        sum += e;
    }
    float inv = 1.f / sum;

    float4 acc = make_float4(0.f, 0.f, 0.f, 0.f);
#pragma unroll
    for (int j = 0; j < KNBR; j++) {
        float w = s[j] * inv;
        float2 v0 = __half22float2(*reinterpret_cast<__half2*>(&vraw[j].x));
        float2 v1 = __half22float2(*reinterpret_cast<__half2*>(&vraw[j].y));
        acc.x += w * v0.x;
        acc.y += w * v0.y;
        acc.z += w * v1.x;
        acc.w += w * v1.y;
    }
    __half2 o0 = __floats2half2_rn(acc.x, acc.y);
    __half2 o1 = __floats2half2_rn(acc.z, acc.w);
    uint2 pk;
    pk.x = *reinterpret_cast<unsigned*>(&o0);
    pk.y = *reinterpret_cast<unsigned*>(&o1);
    reinterpret_cast<uint2*>(g_att)[warp * 32 + lane] = pk;
}

// ---------------------------------------------------------------------------
// Launch: A (QKV, grid.y=3) -> B (attention) -> C (output proj).
// Inputs: x, neighbors, Wq, bq, Wk, bk, Wv, bv, Wo, bo
// ---------------------------------------------------------------------------
extern "C" void kernel_launch(void* const* d_in, const int* in_sizes, int n_in,
                              void* d_out, int out_size) {
    const float* x    = (const float*)d_in[0];
    const int*   nbrs = (const int*)d_in[1];
    const float* Wq   = (const float*)d_in[2];
    const float* bq   = (const float*)d_in[3];
    const float* Wk   = (const float*)d_in[4];
    const float* bk   = (const float*)d_in[5];
    const float* Wv   = (const float*)d_in[6];
    const float* bv   = (const float*)d_in[7];
    const float* Wo   = (const float*)d_in[8];
    const float* bo   = (const float*)d_in[9];
    float*       out  = (float*)d_out;

    int N = in_sizes[0] / D;   // 50000

    // Opt into >48KB dynamic smem (non-stream call; capture-legal).
    cudaFuncSetAttribute(qkv_kernel,
                         cudaFuncAttributeMaxDynamicSharedMemorySize,
                         FUSED_SMEM_BYTES);
    cudaFuncSetAttribute(out_kernel,
                         cudaFuncAttributeMaxDynamicSharedMemorySize,
                         FUSED_SMEM_BYTES);

    dim3 gA((N + TM - 1) / TM, 3);
    qkv_kernel<<<gA, 256, FUSED_SMEM_BYTES>>>(x, Wq, bq, Wk, bk, Wv, bv, N);

    int blocksB = (N + 7) / 8;  // 8 warps / block
    attn_kernel<<<blocksB, 256>>>(nbrs, N);

    out_kernel<<<(N + TM - 1) / TM, 256, FUSED_SMEM_BYTES>>>(Wo, bo, out, N);
}